// round 3
// baseline (speedup 1.0000x reference)
#include <cuda_runtime.h>
#include <cstdint>

// Problem constants (fixed by the dataset):
//   x:        (B=16, D=512, H=32, W=32)  float32
//   p_mu:     (N=16384, D=512)           float32
//   p_logvar: (N=16384, D=512)           float32
//   out:      scalar float32
#define DD      512
#define HWSZ    1024            // H*W
#define NB      16
#define NN      (NB * HWSZ)     // 16384 tokens
#define BI      64              // tokens per block
#define CHUNK   32              // d-columns per chunk
#define NCHUNK  (DD / CHUNK)    // 16
#define NBLOCKS (NN / BI)       // 256

// Global fp64 accumulators. Zero at module load; the finalize kernel resets
// them after consuming, so every graph replay starts from a clean state.
__device__ double g_sx[DD];      // sum_i x[i,d]
__device__ double g_sx2[DD];     // sum_i x[i,d]^2
__device__ double g_siv[DD];     // sum_i inv_var[i,d]
__device__ double g_smuiv[DD];   // sum_i mu[i,d]*inv_var[i,d]
__device__ double g_P;           // sum (x-mu)^2 * inv_var
__device__ double g_R;           // sum mu^2 * inv_var

__global__ __launch_bounds__(1024)
void club_main(const float* __restrict__ x,
               const float* __restrict__ mu,
               const float* __restrict__ lv)
{
    const int tid  = threadIdx.x;
    const int lane = tid & 31;
    const int warp = tid >> 5;           // 0..31

    const int i0  = blockIdx.x * BI;     // token base for this block
    const int b   = i0 / HWSZ;           // batch index (BI divides HWSZ)
    const int hw0 = i0 % HWSZ;

    // x[b, d, hw0 + ii] = xb[d*HWSZ + ii]
    const float* xb = x + (size_t)b * DD * HWSZ + hw0;

    // mu/iv tiles, stored load-orientation [row=i][col=d-in-chunk],
    // read transposed: [ii][warp] -> stride 33 -> conflict-free.
    __shared__ float ms[BI][33];
    __shared__ float vs[BI][33];
    __shared__ double sred[32];

    // Prefetch chunk 0 (each warp owns rows {warp, warp+32}, lane = d col)
    float pm[2], pl[2];
#pragma unroll
    for (int j = 0; j < 2; j++) {
        const int row = warp + 32 * j;
        const size_t off = (size_t)(i0 + row) * DD + lane;   // d0 = 0
        pm[j] = __ldg(&mu[off]);
        pl[j] = __ldg(&lv[off]);
    }

    double accP = 0.0, accR = 0.0;

    for (int c = 0; c < NCHUNK; c++) {
        const int d0 = c * CHUNK;

        // Commit prefetched mu / inv_var tile to SMEM
#pragma unroll
        for (int j = 0; j < 2; j++) {
            const int row = warp + 32 * j;
            ms[row][lane] = pm[j];
            vs[row][lane] = __expf(-pl[j]);
        }
        __syncthreads();

        // Issue next chunk's loads early (latency hidden behind compute)
        if (c + 1 < NCHUNK) {
            const int dn = d0 + CHUNK;
#pragma unroll
            for (int j = 0; j < 2; j++) {
                const int row = warp + 32 * j;
                const size_t off = (size_t)(i0 + row) * DD + dn + lane;
                pm[j] = __ldg(&mu[off]);
                pl[j] = __ldg(&lv[off]);
            }
        }

        // Compute: this warp owns d = d0 + warp; lanes sweep tokens.
        const float* xr = xb + (size_t)(d0 + warp) * HWSZ;
        float a_x = 0.f, a_x2 = 0.f, a_iv = 0.f, a_miv = 0.f;
        float pc = 0.f, rc = 0.f;
#pragma unroll
        for (int j = 0; j < 2; j++) {
            const int ii = j * 32 + lane;
            const float xv = __ldg(&xr[ii]);
            const float m  = ms[ii][warp];
            const float iv = vs[ii][warp];
            const float dx = xv - m;
            pc  += dx * dx * iv;
            rc  += m * m * iv;
            a_x += xv;  a_x2 += xv * xv;
            a_iv += iv; a_miv += m * iv;
        }
        accP += (double)pc;
        accR += (double)rc;

        // Warp-reduce the per-d partial sums over tokens (lanes)
#pragma unroll
        for (int o = 16; o > 0; o >>= 1) {
            a_x   += __shfl_down_sync(0xffffffffu, a_x,   o);
            a_x2  += __shfl_down_sync(0xffffffffu, a_x2,  o);
            a_iv  += __shfl_down_sync(0xffffffffu, a_iv,  o);
            a_miv += __shfl_down_sync(0xffffffffu, a_miv, o);
        }
        if (lane == 0) {
            const int d = d0 + warp;
            atomicAdd(&g_sx[d],    (double)a_x);
            atomicAdd(&g_sx2[d],   (double)a_x2);
            atomicAdd(&g_siv[d],   (double)a_iv);
            atomicAdd(&g_smuiv[d], (double)a_miv);
        }
        __syncthreads();   // protect SMEM tile before next overwrite
    }

    // Block-reduce accP / accR (fp64), one atomic per block per scalar
#pragma unroll
    for (int o = 16; o > 0; o >>= 1) {
        accP += __shfl_down_sync(0xffffffffu, accP, o);
        accR += __shfl_down_sync(0xffffffffu, accR, o);
    }
    if (lane == 0) sred[warp] = accP;
    __syncthreads();
    if (warp == 0) {
        double v = sred[lane];
#pragma unroll
        for (int o = 16; o > 0; o >>= 1) v += __shfl_down_sync(0xffffffffu, v, o);
        if (lane == 0) atomicAdd(&g_P, v);
    }
    __syncthreads();
    if (lane == 0) sred[warp] = accR;
    __syncthreads();
    if (warp == 0) {
        double v = sred[lane];
#pragma unroll
        for (int o = 16; o > 0; o >>= 1) v += __shfl_down_sync(0xffffffffu, v, o);
        if (lane == 0) atomicAdd(&g_R, v);
    }
}

// Combine Q from per-d sums, emit loss, and reset all accumulators so the
// next graph replay starts from zero.
__global__ void club_final(float* __restrict__ out)
{
    const int d = threadIdx.x;           // 512 threads, 1 block
    const double invN = 1.0 / (double)NN;

    double q = (g_sx2[d] * invN) * g_siv[d]
             - 2.0 * (g_sx[d] * invN) * g_smuiv[d];

    // Reset per-d accumulators for next replay
    g_sx[d] = 0.0; g_sx2[d] = 0.0; g_siv[d] = 0.0; g_smuiv[d] = 0.0;

    __shared__ double s[16];
    const int lane = d & 31;
    const int warp = d >> 5;
#pragma unroll
    for (int o = 16; o > 0; o >>= 1) q += __shfl_down_sync(0xffffffffu, q, o);
    if (lane == 0) s[warp] = q;
    __syncthreads();
    if (warp == 0) {
        double v = (lane < 16) ? s[lane] : 0.0;
#pragma unroll
        for (int o = 8; o > 0; o >>= 1) v += __shfl_down_sync(0xffffffffu, v, o);
        if (lane == 0) {
            const double Q = v + g_R;
            const double P = g_P;
            out[0] = (float)(-0.5 * invN * (P - Q));
            g_P = 0.0;
            g_R = 0.0;
        }
    }
}

extern "C" void kernel_launch(void* const* d_in, const int* in_sizes, int n_in,
                              void* d_out, int out_size)
{
    const float* x  = (const float*)d_in[0];   // (16, 512, 32, 32)
    const float* mu = (const float*)d_in[1];   // (16384, 512)
    const float* lv = (const float*)d_in[2];   // (16384, 512)
    float* out = (float*)d_out;                // scalar

    club_main<<<NBLOCKS, 1024>>>(x, mu, lv);
    club_final<<<1, 512>>>(out);
}

// round 4
// speedup vs baseline: 1.7340x; 1.7340x over previous
#include <cuda_runtime.h>
#include <cstdint>

// Problem constants (fixed by the dataset):
//   x:        (B=16, D=512, H=32, W=32)  float32
//   p_mu:     (N=16384, D=512)           float32
//   p_logvar: (N=16384, D=512)           float32
//   out:      scalar float32
#define DD      512
#define HWSZ    1024            // H*W
#define NN      16384           // tokens
#define BI      64              // tokens per block
#define CHUNK   64              // d-columns per chunk
#define NCHUNK  8               // DD / CHUNK
#define NBLOCKS 256             // NN / BI
#define SROW    65              // padded smem row stride (floats), odd -> conflict-light

// Global fp64 accumulators. Zero at module load; club_final resets them after
// consuming, so every graph replay starts from a clean state.
__device__ double g_sx[DD];      // sum_i x[i,d]
__device__ double g_sx2[DD];     // sum_i x[i,d]^2
__device__ double g_siv[DD];     // sum_i inv_var[i,d]
__device__ double g_smuiv[DD];   // sum_i mu[i,d]*inv_var[i,d]
__device__ double g_P;           // sum (x-mu)^2 * inv_var
__device__ double g_R;           // sum mu^2 * inv_var

__global__ __launch_bounds__(1024)
void club_main(const float* __restrict__ x,
               const float* __restrict__ mu,
               const float* __restrict__ lv)
{
    const int tid  = threadIdx.x;
    const int lane = tid & 31;
    const int warp = tid >> 5;            // 0..31

    const int i0  = blockIdx.x * BI;      // token base
    const int b   = i0 / HWSZ;
    const int hw0 = i0 % HWSZ;
    const float* xb = x + (size_t)b * DD * HWSZ + hw0;

    // Tile: BI tokens x CHUNK d, padded rows (stride 65 floats).
    __shared__ float ms[BI * SROW];
    __shared__ float vs[BI * SROW];
    __shared__ double sred[32];

    // --- load-role indexing: thread -> (row, 4-wide d group) ---
    const int lrow = tid >> 4;            // 0..63 token row
    const int ld4  = (tid & 15) * 4;      // d offset within chunk (0,4,..,60)
    const size_t lbase = (size_t)(i0 + lrow) * DD + ld4;

    // --- compute-role indexing: warp owns 2 d-cols; 16 lanes x float4 tokens ---
    const int dl  = 2 * warp + (lane >> 4);   // 0..63 d within chunk
    const int ii4 = (lane & 15) * 4;          // token base 0,4,..,60

    // Prefetch chunk 0 (rotated start to de-burst atomics & DRAM pages)
    int cidx = blockIdx.x & (NCHUNK - 1);
    float4 pm = __ldg((const float4*)(mu + lbase + cidx * CHUNK));
    float4 pl = __ldg((const float4*)(lv + lbase + cidx * CHUNK));

    double accP = 0.0, accR = 0.0;

    for (int c = 0; c < NCHUNK; c++) {
        const int d0 = cidx * CHUNK;

        // Commit tile: mu and inv_var = exp(-logvar)
        {
            float* mrow = ms + lrow * SROW + ld4;
            float* vrow = vs + lrow * SROW + ld4;
            mrow[0] = pm.x; mrow[1] = pm.y; mrow[2] = pm.z; mrow[3] = pm.w;
            vrow[0] = __expf(-pl.x); vrow[1] = __expf(-pl.y);
            vrow[2] = __expf(-pl.z); vrow[3] = __expf(-pl.w);
        }
        __syncthreads();

        // Prefetch next chunk early (covers DRAM latency with compute below)
        const int cnext = (cidx + 1) & (NCHUNK - 1);
        if (c + 1 < NCHUNK) {
            pm = __ldg((const float4*)(mu + lbase + cnext * CHUNK));
            pl = __ldg((const float4*)(lv + lbase + cnext * CHUNK));
        }

        // Compute: vector x load + transposed SMEM reads
        const float4 xv4 = __ldg((const float4*)(xb + (size_t)(d0 + dl) * HWSZ + ii4));
        float a_x = 0.f, a_x2 = 0.f, a_iv = 0.f, a_miv = 0.f;
        float pc = 0.f, rc = 0.f;

        const float xvals[4] = {xv4.x, xv4.y, xv4.z, xv4.w};
#pragma unroll
        for (int k = 0; k < 4; k++) {
            const int ii = ii4 + k;
            const float m  = ms[ii * SROW + dl];
            const float iv = vs[ii * SROW + dl];
            const float xv = xvals[k];
            const float dx = xv - m;
            pc   += dx * dx * iv;
            rc   += m * m * iv;
            a_x  += xv;  a_x2  += xv * xv;
            a_iv += iv;  a_miv += m * iv;
        }
        accP += (double)pc;
        accR += (double)rc;

        // Reduce the per-d sums over the 16 token-lanes (width-16 segments)
#pragma unroll
        for (int o = 8; o > 0; o >>= 1) {
            a_x   += __shfl_down_sync(0xffffffffu, a_x,   o, 16);
            a_x2  += __shfl_down_sync(0xffffffffu, a_x2,  o, 16);
            a_iv  += __shfl_down_sync(0xffffffffu, a_iv,  o, 16);
            a_miv += __shfl_down_sync(0xffffffffu, a_miv, o, 16);
        }
        if ((lane & 15) == 0) {
            const int d = d0 + dl;
            atomicAdd(&g_sx[d],    (double)a_x);
            atomicAdd(&g_sx2[d],   (double)a_x2);
            atomicAdd(&g_siv[d],   (double)a_iv);
            atomicAdd(&g_smuiv[d], (double)a_miv);
        }
        __syncthreads();   // protect SMEM before next overwrite
        cidx = cnext;
    }

    // Block-reduce accP / accR (fp64), one atomic per block per scalar
#pragma unroll
    for (int o = 16; o > 0; o >>= 1) {
        accP += __shfl_down_sync(0xffffffffu, accP, o);
        accR += __shfl_down_sync(0xffffffffu, accR, o);
    }
    if (lane == 0) sred[warp] = accP;
    __syncthreads();
    if (warp == 0) {
        double v = sred[lane];
#pragma unroll
        for (int o = 16; o > 0; o >>= 1) v += __shfl_down_sync(0xffffffffu, v, o);
        if (lane == 0) atomicAdd(&g_P, v);
    }
    __syncthreads();
    if (lane == 0) sred[warp] = accR;
    __syncthreads();
    if (warp == 0) {
        double v = sred[lane];
#pragma unroll
        for (int o = 16; o > 0; o >>= 1) v += __shfl_down_sync(0xffffffffu, v, o);
        if (lane == 0) atomicAdd(&g_R, v);
    }
}

// Combine Q from per-d sums, emit loss, reset accumulators for next replay.
__global__ void club_final(float* __restrict__ out)
{
    const int d = threadIdx.x;           // 512 threads, 1 block
    const double invN = 1.0 / (double)NN;

    double q = (g_sx2[d] * invN) * g_siv[d]
             - 2.0 * (g_sx[d] * invN) * g_smuiv[d];

    g_sx[d] = 0.0; g_sx2[d] = 0.0; g_siv[d] = 0.0; g_smuiv[d] = 0.0;

    __shared__ double s[16];
    const int lane = d & 31;
    const int warp = d >> 5;
#pragma unroll
    for (int o = 16; o > 0; o >>= 1) q += __shfl_down_sync(0xffffffffu, q, o);
    if (lane == 0) s[warp] = q;
    __syncthreads();
    if (warp == 0) {
        double v = (lane < 16) ? s[lane] : 0.0;
#pragma unroll
        for (int o = 8; o > 0; o >>= 1) v += __shfl_down_sync(0xffffffffu, v, o);
        if (lane == 0) {
            const double Q = v + g_R;
            const double P = g_P;
            out[0] = (float)(-0.5 * invN * (P - Q));
            g_P = 0.0;
            g_R = 0.0;
        }
    }
}

extern "C" void kernel_launch(void* const* d_in, const int* in_sizes, int n_in,
                              void* d_out, int out_size)
{
    const float* x  = (const float*)d_in[0];   // (16, 512, 32, 32)
    const float* mu = (const float*)d_in[1];   // (16384, 512)
    const float* lv = (const float*)d_in[2];   // (16384, 512)
    float* out = (float*)d_out;                // scalar

    club_main<<<NBLOCKS, 1024>>>(x, mu, lv);
    club_final<<<1, 512>>>(out);
}

// round 6
// speedup vs baseline: 2.1144x; 1.2193x over previous
#include <cuda_runtime.h>
#include <cstdint>

// x: (16, 512, 32, 32) f32 | p_mu, p_logvar: (16384, 512) f32 | out: scalar f32
#define DD      512
#define HWSZ    1024
#define NN      16384
#define TPB     64              // tokens per block
#define STEPS   8               // token steps per block (8 tokens each)
#define NBLOCKS 256
#define SROW    516             // padded row stride (floats) for x tile [8][SROW]

__device__ double g_sx[DD];
__device__ double g_sx2[DD];
__device__ double g_siv[DD];
__device__ double g_smuiv[DD];
__device__ double g_P;
__device__ double g_R;
__device__ int    g_done;       // arrival counter; reset by finalizer

__global__ __launch_bounds__(1024)
void club_fused(const float* __restrict__ x,
                const float* __restrict__ mu,
                const float* __restrict__ lv,
                float* __restrict__ out)
{
    const int tid  = threadIdx.x;
    const int lane = tid & 31;
    const int warp = tid >> 5;
    const int ts   = tid >> 7;          // token lane 0..7
    const int dg   = tid & 127;         // d-group: d = 4*dg..4*dg+3 (fixed all block)

    const int i0  = blockIdx.x * TPB;
    const int b   = i0 >> 10;
    const int hw0 = i0 & (HWSZ - 1);
    const float* xb = x + (size_t)b * DD * HWSZ + hw0;

    __shared__ float  xs[2][STEPS * SROW];   // x tiles, [token row][d col]
    __shared__ double sred[32];
    __shared__ int    s_last;

    // ---- x loader role: thread -> (d row, 4-token group) ----
    const int ld = tid >> 1;                 // d row 0..511
    const int lh = (tid & 1) * 4;            // hw offset 0 or 4
    const float* xlp = xb + (size_t)ld * HWSZ + lh;

    // tile 0 -> buf0 (transposed store; conflict-free)
    float4 xt = __ldg((const float4*)xlp);
    {
        float* bse = &xs[0][0];
        bse[(lh + 0) * SROW + ld] = xt.x;
        bse[(lh + 1) * SROW + ld] = xt.y;
        bse[(lh + 2) * SROW + ld] = xt.z;
        bse[(lh + 3) * SROW + ld] = xt.w;
    }
    xt = __ldg((const float4*)(xlp + 8));    // tile 1 in regs

    // ---- mu/lv depth-2 register pipeline (coalesced float4) ----
    const size_t mb = (size_t)(i0 + ts) * DD + 4 * dg;
    float4 pm[2], pl[2];
    pm[0] = __ldg((const float4*)(mu + mb));
    pl[0] = __ldg((const float4*)(lv + mb));
    pm[1] = __ldg((const float4*)(mu + mb + 8 * DD));
    pl[1] = __ldg((const float4*)(lv + mb + 8 * DD));

    float ax0=0.f,ax1=0.f,ax2_=0.f,ax3=0.f;
    float b0=0.f,b1=0.f,b2=0.f,b3=0.f;        // x^2 sums
    float v0=0.f,v1=0.f,v2=0.f,v3=0.f;        // iv sums
    float w0=0.f,w1=0.f,w2=0.f,w3=0.f;        // mu*iv sums
    float accP = 0.f, accR = 0.f;

#pragma unroll
    for (int s = 0; s < STEPS; s++) {
        __syncthreads();                      // tile s ready; buf[(s+1)&1] free

        // commit tile s+1, prefetch tile s+2
        if (s < STEPS - 1) {
            float* bse = &xs[(s + 1) & 1][0];
            bse[(lh + 0) * SROW + ld] = xt.x;
            bse[(lh + 1) * SROW + ld] = xt.y;
            bse[(lh + 2) * SROW + ld] = xt.z;
            bse[(lh + 3) * SROW + ld] = xt.w;
            if (s < STEPS - 2) xt = __ldg((const float4*)(xlp + 8 * (s + 2)));
        }

        const float4 cm = pm[s & 1];
        const float4 cl = pl[s & 1];
        if (s < STEPS - 2) {
            pm[s & 1] = __ldg((const float4*)(mu + mb + (size_t)(s + 2) * 8 * DD));
            pl[s & 1] = __ldg((const float4*)(lv + mb + (size_t)(s + 2) * 8 * DD));
        }

        // x for (token ts of tile s, d = 4dg..4dg+3): one conflict-free LDS.128
        const float4 xv = *(const float4*)&xs[s & 1][ts * SROW + 4 * dg];

        const float i0v = __expf(-cl.x), i1v = __expf(-cl.y);
        const float i2v = __expf(-cl.z), i3v = __expf(-cl.w);

        float dx;
        dx = xv.x - cm.x; accP += dx*dx*i0v; accR += cm.x*cm.x*i0v;
        ax0 += xv.x; b0 += xv.x*xv.x; v0 += i0v; w0 += cm.x*i0v;
        dx = xv.y - cm.y; accP += dx*dx*i1v; accR += cm.y*cm.y*i1v;
        ax1 += xv.y; b1 += xv.y*xv.y; v1 += i1v; w1 += cm.y*i1v;
        dx = xv.z - cm.z; accP += dx*dx*i2v; accR += cm.z*cm.z*i2v;
        ax2_ += xv.z; b2 += xv.z*xv.z; v2 += i2v; w2 += cm.z*i2v;
        dx = xv.w - cm.w; accP += dx*dx*i3v; accR += cm.w*cm.w*i3v;
        ax3 += xv.w; b3 += xv.w*xv.w; v3 += i3v; w3 += cm.w*i3v;
    }

    // ---- block-reduce P / R (fp64), one atomic each ----
    double dP = (double)accP, dR = (double)accR;
#pragma unroll
    for (int o = 16; o > 0; o >>= 1) {
        dP += __shfl_down_sync(0xffffffffu, dP, o);
        dR += __shfl_down_sync(0xffffffffu, dR, o);
    }
    if (lane == 0) sred[warp] = dP;
    __syncthreads();
    if (warp == 0) {
        double t = sred[lane];
#pragma unroll
        for (int o = 16; o > 0; o >>= 1) t += __shfl_down_sync(0xffffffffu, t, o);
        if (lane == 0) atomicAdd(&g_P, t);
    }
    __syncthreads();
    if (lane == 0) sred[warp] = dR;
    __syncthreads();
    if (warp == 0) {
        double t = sred[lane];
#pragma unroll
        for (int o = 16; o > 0; o >>= 1) t += __shfl_down_sync(0xffffffffu, t, o);
        if (lane == 0) atomicAdd(&g_R, t);
    }

    // ---- per-d stats: two SMEM rounds (reuse x buffers), fp64 atomics once ----
    __syncthreads();
    *(float4*)&xs[0][ts * SROW + 4 * dg] = make_float4(ax0, ax1, ax2_, ax3);
    *(float4*)&xs[1][ts * SROW + 4 * dg] = make_float4(b0, b1, b2, b3);
    __syncthreads();
    if (tid < DD) {
        float s1 = 0.f, s2 = 0.f;
#pragma unroll
        for (int t = 0; t < 8; t++) { s1 += xs[0][t * SROW + tid]; s2 += xs[1][t * SROW + tid]; }
        atomicAdd(&g_sx[tid],  (double)s1);
        atomicAdd(&g_sx2[tid], (double)s2);
    }
    __syncthreads();
    *(float4*)&xs[0][ts * SROW + 4 * dg] = make_float4(v0, v1, v2, v3);
    *(float4*)&xs[1][ts * SROW + 4 * dg] = make_float4(w0, w1, w2, w3);
    __syncthreads();
    if (tid < DD) {
        float s1 = 0.f, s2 = 0.f;
#pragma unroll
        for (int t = 0; t < 8; t++) { s1 += xs[0][t * SROW + tid]; s2 += xs[1][t * SROW + tid]; }
        atomicAdd(&g_siv[tid],   (double)s1);
        atomicAdd(&g_smuiv[tid], (double)s2);
    }

    // ---- fused finalize: last-arriving block combines & resets ----
    __threadfence();
    if (tid == 0) s_last = (atomicAdd(&g_done, 1) == NBLOCKS - 1) ? 1 : 0;
    __syncthreads();
    if (s_last) {
        __threadfence();
        const double invN = 1.0 / (double)NN;
        double q = 0.0;
        if (tid < DD) {
            q = (g_sx2[tid] * invN) * g_siv[tid]
              - 2.0 * (g_sx[tid] * invN) * g_smuiv[tid];
            g_sx[tid] = 0.0; g_sx2[tid] = 0.0; g_siv[tid] = 0.0; g_smuiv[tid] = 0.0;
        }
#pragma unroll
        for (int o = 16; o > 0; o >>= 1) q += __shfl_down_sync(0xffffffffu, q, o);
        if (lane == 0) sred[warp] = q;
        __syncthreads();
        if (warp == 0) {
            double t = (lane < 16) ? sred[lane] : 0.0;
#pragma unroll
            for (int o = 8; o > 0; o >>= 1) t += __shfl_down_sync(0xffffffffu, t, o);
            if (lane == 0) {
                const double Q = t + g_R;
                out[0] = (float)(-0.5 * invN * (g_P - Q));
                g_P = 0.0; g_R = 0.0; g_done = 0;
            }
        }
    }
}

extern "C" void kernel_launch(void* const* d_in, const int* in_sizes, int n_in,
                              void* d_out, int out_size)
{
    const float* x  = (const float*)d_in[0];
    const float* mu = (const float*)d_in[1];
    const float* lv = (const float*)d_in[2];
    float* out = (float*)d_out;

    club_fused<<<NBLOCKS, 1024>>>(x, mu, lv, out);
}